// round 15
// baseline (speedup 1.0000x reference)
#include <cuda_runtime.h>
#include <cuda_fp16.h>
#include <stdint.h>

// 3-kernel pipeline (single stream):
//  1) gather_kernel : temp fp32 -> g_qkv[win][qkv][t][d] fp16; Q pre-scaled by SCALE*log2e
//  2) attn_kernel   : streaming no-max softmax attention + fused LePE -> g_o16 fp16
//                     f16-acc QK MMA; ones-column MMA row-sums; pipelined staging;
//                     NOW half-window per CTA (grid 2048), ONE strip per warp
//                     (per-warp serial path halved again vs round 14)
//  3) scatter_kernel: g_o16 -> out (B,C,H,W); shuffle-paired STS.32 transpose, STG.128

#define SMEM_A 19456   // half[4][64][38]
#define SMEM_B 42240   // sK/sV half[256][40] + sW2 float2[16][9] + sB2 float2[16]
#define SMEM_C 33920   // half[32][530]  (c-stride 530, h-stride 66)

__device__ __half g_qkv[1024u * 3u * 256u * 32u];  // 48 MB
__device__ __half g_o16[1024u * 256u * 32u];       // 16 MB

__device__ __forceinline__ void ldm4(uint32_t a, uint32_t& r0, uint32_t& r1,
                                     uint32_t& r2, uint32_t& r3) {
    asm volatile("ldmatrix.sync.aligned.m8n8.x4.shared.b16 {%0,%1,%2,%3}, [%4];"
                 : "=r"(r0), "=r"(r1), "=r"(r2), "=r"(r3) : "r"(a));
}
__device__ __forceinline__ void ldm4t(uint32_t a, uint32_t& r0, uint32_t& r1,
                                      uint32_t& r2, uint32_t& r3) {
    asm volatile("ldmatrix.sync.aligned.m8n8.x4.trans.shared.b16 {%0,%1,%2,%3}, [%4];"
                 : "=r"(r0), "=r"(r1), "=r"(r2), "=r"(r3) : "r"(a));
}
// fp32-accumulator MMA (PV + ones-column row sums)
__device__ __forceinline__ void mma16816(float* c,
                                         uint32_t a0, uint32_t a1, uint32_t a2, uint32_t a3,
                                         uint32_t b0, uint32_t b1) {
    asm volatile("mma.sync.aligned.m16n8k16.row.col.f32.f16.f16.f32 "
                 "{%0,%1,%2,%3},{%4,%5,%6,%7},{%8,%9},{%0,%1,%2,%3};"
                 : "+f"(c[0]), "+f"(c[1]), "+f"(c[2]), "+f"(c[3])
                 : "r"(a0), "r"(a1), "r"(a2), "r"(a3), "r"(b0), "r"(b1));
}
// fp16-accumulator MMA (QK): D layout = {col tg2, tg2+1} half2 per lane
__device__ __forceinline__ void mma16816h(uint32_t& d0, uint32_t& d1,
                                          uint32_t a0, uint32_t a1, uint32_t a2, uint32_t a3,
                                          uint32_t b0, uint32_t b1) {
    asm volatile("mma.sync.aligned.m16n8k16.row.col.f16.f16.f16.f16 "
                 "{%0,%1},{%2,%3,%4,%5},{%6,%7},{%0,%1};"
                 : "+r"(d0), "+r"(d1)
                 : "r"(a0), "r"(a1), "r"(a2), "r"(a3), "r"(b0), "r"(b1));
}
__device__ __forceinline__ uint32_t ex2h2(uint32_t x) {
    asm("ex2.approx.f16x2 %0, %1;" : "=r"(x) : "r"(x));
    return x;
}
__device__ __forceinline__ void cpa16(uint32_t dst, const void* src) {
    asm volatile("cp.async.ca.shared.global [%0], [%1], 16;" :: "r"(dst), "l"(src));
}
__device__ __forceinline__ uint32_t ld32h(const __half* p) {
    return *reinterpret_cast<const uint32_t*>(p);
}

// ---------------------------------------------------------------------------
// Kernel 1: gather + layout transform.  grid = 8b*3p*8head*16h4 = 3072
// ---------------------------------------------------------------------------
__global__ void __launch_bounds__(256)
gather_kernel(const float* __restrict__ temp)
{
    extern __shared__ __half tileA[];  // [4 h][64 w][38 c-padded]
    const int bid = blockIdx.x, tid = threadIdx.x;
    const int h16  = bid & 15;
    const int head = (bid >> 4) & 7;
    const int bp   = bid >> 7;          // b*3 + p
    const int p    = bp % 3;
    const int b    = bp / 3;

    const size_t base = ((size_t)bp * 256 + head * 32) * 4096 + (size_t)(h16 * 4) * 64;
    // Q carries SCALE * log2(e) so QK^T lands directly in the exp2 domain
    const float scale = (p == 0) ? (0.17677669529663687f * 1.4426950408889634f) : 1.0f;

#pragma unroll
    for (int j = tid; j < 1024; j += 256) {
        const int w4 = j & 15, h = (j >> 4) & 3, c2 = j >> 6;
        const int c = c2 * 2;
        const float4 va = *reinterpret_cast<const float4*>(
            temp + base + (size_t)c * 4096 + h * 64 + w4 * 4);
        const float4 vb = *reinterpret_cast<const float4*>(
            temp + base + (size_t)(c + 1) * 4096 + h * 64 + w4 * 4);
        const int sb = (h * 64 + w4 * 4) * 38 + c;
        *reinterpret_cast<__half2*>(&tileA[sb])       = __floats2half2_rn(va.x * scale, vb.x * scale);
        *reinterpret_cast<__half2*>(&tileA[sb + 38])  = __floats2half2_rn(va.y * scale, vb.y * scale);
        *reinterpret_cast<__half2*>(&tileA[sb + 76])  = __floats2half2_rn(va.z * scale, vb.z * scale);
        *reinterpret_cast<__half2*>(&tileA[sb + 114]) = __floats2half2_rn(va.w * scale, vb.w * scale);
    }
    __syncthreads();

    // phase 2: 8 lanes per token, uint2 (8B) stores
    const int wb = (b * 8 + head) * 16;
    const int d  = (tid & 7) * 4;
#pragma unroll
    for (int pp = tid >> 3; pp < 256; pp += 32) {
        const int h = pp >> 6, w = pp & 63;
        const int win = wb + (w & 15);
        const int t   = (h16 * 4 + h) * 4 + (w >> 4);
        const int sb  = (h * 64 + w) * 38 + d;
        uint2 val;
        val.x = *reinterpret_cast<const uint32_t*>(&tileA[sb]);
        val.y = *reinterpret_cast<const uint32_t*>(&tileA[sb + 2]);
        *reinterpret_cast<uint2*>(&g_qkv[(((size_t)win * 3 + p) * 256 + t) * 32 + d]) = val;
    }
}

// ---------------------------------------------------------------------------
// Kernel 2: streaming attention + fused LePE.  grid = 2048 half-windows,
//           256 thr / 8 warps, ONE 16-row strip per warp
// ---------------------------------------------------------------------------
__global__ void __launch_bounds__(256, 2)
attn_kernel(const float* __restrict__ wgt, const float* __restrict__ bias)
{
    const int win  = blockIdx.x >> 1;
    const int half = blockIdx.x & 1;
    const int tid  = threadIdx.x;
    const int lane = tid & 31;
    const int wid  = tid >> 5;          // 0..7

    extern __shared__ char smem[];
    __half* sK  = reinterpret_cast<__half*>(smem);            // [256][40]
    __half* sV  = reinterpret_cast<__half*>(smem + 20480);    // [256][40]
    float2* sW2 = reinterpret_cast<float2*>(smem + 40960);    // [16 chpair][9 tap]
    float2* sB2 = reinterpret_cast<float2*>(smem + 42112);    // [16]

    const int head  = (win >> 4) & 7;
    const int cbase = head * 32;

    const uint32_t kb = (uint32_t)__cvta_generic_to_shared(sK);
    const uint32_t vb = (uint32_t)__cvta_generic_to_shared(sV);

    const __half* qkvg = g_qkv + (size_t)win * 3u * 8192u;
    const uint4* srcK = reinterpret_cast<const uint4*>(qkvg + 8192);
    const uint4* srcV = reinterpret_cast<const uint4*>(qkvg + 16384);

    // pipelined staging: 4 commit groups of 64 tokens (256 uint4), 1 iter each
#pragma unroll
    for (int gr = 0; gr < 4; ++gr) {
        const int j = gr * 256 + tid;
        const int t = j >> 2, dd = (j & 3) * 8;
        const uint32_t off = (uint32_t)(t * 40 + dd) * 2;
        cpa16(kb + off, srcK + j);
        cpa16(vb + off, srcV + j);
        asm volatile("cp.async.commit_group;");
    }

    // overlap with async window: channel-paired conv weights/bias + Q frags
    if (tid < 144) {
        const int cp = tid / 9, k = tid % 9;
        sW2[tid] = make_float2(wgt[(cbase + 2 * cp) * 9 + k],
                               wgt[(cbase + 2 * cp + 1) * 9 + k]);
    }
    if (tid < 16) sB2[tid] = make_float2(bias[cbase + 2 * tid],
                                         bias[cbase + 2 * tid + 1]);

    const int g   = lane >> 2;
    const int tg2 = (lane & 3) << 1;

    // per-warp Q fragments for its single strip (rows half*128 + wid*16 ..+15)
    const int r0 = half * 128 + wid * 16;
    uint32_t qf[8];
    {
        const __half* q0 = qkvg + (r0 + g) * 32 + tg2;
        const __half* q1 = qkvg + (r0 + g + 8) * 32 + tg2;
        qf[0] = ld32h(q0);      qf[1] = ld32h(q1);
        qf[2] = ld32h(q0 + 8);  qf[3] = ld32h(q1 + 8);
        qf[4] = ld32h(q0 + 16); qf[5] = ld32h(q1 + 16);
        qf[6] = ld32h(q0 + 24); qf[7] = ld32h(q1 + 24);
    }

    // group 0 (tokens 0-63) ready -> start computing
    asm volatile("cp.async.wait_group 3;");
    __syncthreads();

    const int lrow = lane & 15;
    const int lcol = (lane >> 4) << 3;

    // ones-column B fragment: lanes 0-3 own n=0 column (1.0 for all k)
    const uint32_t onesB = ((lane >> 2) == 0) ? 0x3C003C00u : 0u;

    __half* og16 = g_o16 + (size_t)win * 8192;

    float o[4][4];
    float ol[4];
    ol[0] = 0.f; ol[1] = 0.f; ol[2] = 0.f; ol[3] = 0.f;
#pragma unroll
    for (int on = 0; on < 4; ++on) {
        o[on][0] = 0.f; o[on][1] = 0.f; o[on][2] = 0.f; o[on][3] = 0.f;
    }

    uint32_t kf[2][8], vf[2][8];
    ldm4 (kb + (uint32_t)((lrow * 40 + lcol) * 2),        kf[0][0], kf[0][1], kf[0][2], kf[0][3]);
    ldm4 (kb + (uint32_t)((lrow * 40 + 16 + lcol) * 2),   kf[0][4], kf[0][5], kf[0][6], kf[0][7]);
    ldm4t(vb + (uint32_t)((lrow * 40 + lcol) * 2),        vf[0][0], vf[0][1], vf[0][2], vf[0][3]);
    ldm4t(vb + (uint32_t)((lrow * 40 + 16 + lcol) * 2),   vf[0][4], vf[0][5], vf[0][6], vf[0][7]);

#pragma unroll
    for (int kt = 0; kt < 16; ++kt) {
        // progressive staging waits; prefetch of chunk kt+1 crosses groups at 3/7/11
        if (kt == 3)  { asm volatile("cp.async.wait_group 2;"); __syncthreads(); }
        if (kt == 7)  { asm volatile("cp.async.wait_group 1;"); __syncthreads(); }
        if (kt == 11) { asm volatile("cp.async.wait_group 0;"); __syncthreads(); }

        const int cur = kt & 1;
        const int nxt = cur ^ 1;
        if (kt < 15) {
            const uint32_t rb = (uint32_t)(((kt + 1) * 16 + lrow) * 40) * 2;
            ldm4 (kb + rb + lcol * 2,        kf[nxt][0], kf[nxt][1], kf[nxt][2], kf[nxt][3]);
            ldm4 (kb + rb + (16 + lcol) * 2, kf[nxt][4], kf[nxt][5], kf[nxt][6], kf[nxt][7]);
            ldm4t(vb + rb + lcol * 2,        vf[nxt][0], vf[nxt][1], vf[nxt][2], vf[nxt][3]);
            ldm4t(vb + rb + (16 + lcol) * 2, vf[nxt][4], vf[nxt][5], vf[nxt][6], vf[nxt][7]);
        }

        uint32_t s0 = 0u, s1 = 0u, s2 = 0u, s3 = 0u;
        mma16816h(s0, s1, qf[0], qf[1], qf[2], qf[3], kf[cur][0], kf[cur][2]);
        mma16816h(s0, s1, qf[4], qf[5], qf[6], qf[7], kf[cur][4], kf[cur][6]);
        mma16816h(s2, s3, qf[0], qf[1], qf[2], qf[3], kf[cur][1], kf[cur][3]);
        mma16816h(s2, s3, qf[4], qf[5], qf[6], qf[7], kf[cur][5], kf[cur][7]);

        // exp2 directly on the f16 MMA output (log2 domain; no max)
        const uint32_t p0 = ex2h2(s0);
        const uint32_t p1 = ex2h2(s1);
        const uint32_t p2 = ex2h2(s2);
        const uint32_t p3 = ex2h2(s3);

        mma16816(o[0], p0, p1, p2, p3, vf[cur][0], vf[cur][1]);
        mma16816(o[1], p0, p1, p2, p3, vf[cur][2], vf[cur][3]);
        mma16816(o[2], p0, p1, p2, p3, vf[cur][4], vf[cur][5]);
        mma16816(o[3], p0, p1, p2, p3, vf[cur][6], vf[cur][7]);
        mma16816(ol, p0, p1, p2, p3, onesB, onesB);
    }

    {
        const float l0 = __shfl_sync(0xffffffffu, ol[0], lane & 28);
        const float l1 = __shfl_sync(0xffffffffu, ol[2], lane & 28);
        const float inv0 = 1.f / l0;
        const float inv1 = 1.f / l1;

        // epilogue: normalize + LePE conv (float2 weights) + half2 store
#pragma unroll
        for (int on = 0; on < 4; ++on) {
            const int d0 = on * 8 + tg2;
            const float2* wrow = &sW2[(d0 >> 1) * 9];
            const float2  b2   = sB2[d0 >> 1];
#pragma unroll
            for (int ocp = 0; ocp < 4; ocp += 2) {
                const int t  = r0 + g + ((ocp & 2) ? 8 : 0);
                const int ih = t >> 2;
                const int jw = t & 3;
                float a0 = b2.x, a1 = b2.y;
                const int ki0 = (ih == 0) ? 1 : 0;
                const int ki1 = (ih == 63) ? 2 : 3;
#pragma unroll
                for (int ki = 0; ki < 3; ++ki) {
                    if (ki < ki0 || ki >= ki1) continue;
                    const int ii = ih + ki - 1;
#pragma unroll
                    for (int kj = 0; kj < 3; ++kj) {
                        const int jj = jw + kj - 1;
                        if (jj < 0 || jj > 3) continue;
                        const __half2 vv = *reinterpret_cast<const __half2*>(
                            &sV[(ii * 4 + jj) * 40 + d0]);
                        const float2 vf2 = __half22float2(vv);
                        const float2 wv  = wrow[ki * 3 + kj];
                        a0 = fmaf(wv.x, vf2.x, a0);
                        a1 = fmaf(wv.y, vf2.y, a1);
                    }
                }
                const float inv = (ocp & 2) ? inv1 : inv0;
                const __half2 r = __floats2half2_rn(o[on][ocp] * inv + a0,
                                                    o[on][ocp + 1] * inv + a1);
                *reinterpret_cast<__half2*>(&og16[t * 32 + d0]) = r;
            }
        }
    }
}

// ---------------------------------------------------------------------------
// Kernel 3: scatter to (B,C,H,W).  grid = 8(b)*8(head)*8(h8) = 512
// ---------------------------------------------------------------------------
__global__ void __launch_bounds__(256)
scatter_kernel(float* __restrict__ out)
{
    extern __shared__ __half tileC[];  // [32 c][8 h][64 w]: c-stride 530, h-stride 66
    const int bid = blockIdx.x, tid = threadIdx.x;
    const int h8   = bid & 7;
    const int head = (bid >> 3) & 7;
    const int b    = bid >> 6;
    const int h0   = h8 * 8;
    const int lane = tid & 31, wid = tid >> 5;
    const int wb   = (b * 8 + head) * 16;
    const int d0   = (lane & 15) * 2;
    const int hiL  = lane >> 4;

    // phase 1: coalesced reads; shuffle-pair to build w-adjacent half2 of one
    // channel per lane, single STS.32
#pragma unroll
    for (int pp = wid; pp < 256; pp += 8) {
        const int p2 = pp * 2 + hiL;
        const int h = p2 >> 6, w = p2 & 63;
        const int win = wb + (w & 15);
        const int t   = (h0 + h) * 4 + (w >> 4);
        const uint32_t mine = *reinterpret_cast<const uint32_t*>(
            &g_o16[((size_t)win * 256 + t) * 32 + d0]);
        const uint32_t other = __shfl_xor_sync(0xffffffffu, mine, 16);
        uint32_t pairv;
        if (hiL == 0) {
            pairv = (mine & 0xFFFFu) | (other << 16);
        } else {
            pairv = (other >> 16) | (mine & 0xFFFF0000u);
        }
        const int c = d0 + hiL;
        const int weven = w & ~1;
        *reinterpret_cast<uint32_t*>(&tileC[c * 530 + h * 66 + weven]) = pairv;
    }
    __syncthreads();

    // phase 2: vectorized write, STG.128, 512B contiguous per warp
    const size_t ob = ((size_t)b * 256 + head * 32) * 4096 + (size_t)h0 * 64;
#pragma unroll
    for (int j = tid; j < 4096; j += 256) {
        const int w4 = j & 15, h = (j >> 4) & 7, c = j >> 7;
        const int sbase = c * 530 + h * 66 + w4 * 4;
        const float2 fa = __half22float2(*reinterpret_cast<const __half2*>(&tileC[sbase]));
        const float2 fb = __half22float2(*reinterpret_cast<const __half2*>(&tileC[sbase + 2]));
        float4 r;
        r.x = fa.x; r.y = fa.y; r.z = fb.x; r.w = fb.y;
        *reinterpret_cast<float4*>(&out[ob + (size_t)c * 4096 + h * 64 + w4 * 4]) = r;
    }
}

// ---------------------------------------------------------------------------
extern "C" void kernel_launch(void* const* d_in, const int* in_sizes, int n_in,
                              void* d_out, int out_size)
{
    (void)in_sizes; (void)n_in; (void)out_size;
    const float* temp = (const float*)d_in[0];
    const float* wgt  = (const float*)d_in[1];
    const float* bias = (const float*)d_in[2];
    float* out = (float*)d_out;

    cudaFuncSetAttribute(gather_kernel,  cudaFuncAttributeMaxDynamicSharedMemorySize, SMEM_A);
    cudaFuncSetAttribute(attn_kernel,    cudaFuncAttributeMaxDynamicSharedMemorySize, SMEM_B);
    cudaFuncSetAttribute(scatter_kernel, cudaFuncAttributeMaxDynamicSharedMemorySize, SMEM_C);

    gather_kernel<<<3072, 256, SMEM_A>>>(temp);
    attn_kernel<<<2048, 256, SMEM_B>>>(wgt, bias);
    scatter_kernel<<<512, 256, SMEM_C>>>(out);
}

// round 16
// speedup vs baseline: 1.1492x; 1.1492x over previous
#include <cuda_runtime.h>
#include <cuda_fp16.h>
#include <stdint.h>

// 3-kernel pipeline (single stream), attn = round-14 (best known):
//  1) gather_kernel : temp fp32 -> g_qkv[win][qkv][t][d] fp16; Q pre-scaled by SCALE*log2e
//  2) attn_kernel   : streaming no-max softmax attention + fused LePE -> g_o16 fp16
//                     f16-acc QK MMA; ones-column MMA row-sums; pipelined staging;
//                     8 warps/CTA, one strip-pair per warp
//  3) scatter_kernel: g_o16 -> out (B,C,H,W); NOW 4-h-row tiles (grid 1024,
//                     smem 17 KB -> ~8 CTAs/SM) for memory-parallelism
//                     [round-15 half-window attn REVERTED: 2x staging traffic]

#define SMEM_A 19456   // half[4][64][38]
#define SMEM_B 42240   // sK/sV half[256][40] + sW2 float2[16][9] + sB2 float2[16]
#define SMEM_C 17152   // half[32][266]  (c-stride 266, h-stride 66)

__device__ __half g_qkv[1024u * 3u * 256u * 32u];  // 48 MB
__device__ __half g_o16[1024u * 256u * 32u];       // 16 MB

__device__ __forceinline__ void ldm4(uint32_t a, uint32_t& r0, uint32_t& r1,
                                     uint32_t& r2, uint32_t& r3) {
    asm volatile("ldmatrix.sync.aligned.m8n8.x4.shared.b16 {%0,%1,%2,%3}, [%4];"
                 : "=r"(r0), "=r"(r1), "=r"(r2), "=r"(r3) : "r"(a));
}
__device__ __forceinline__ void ldm4t(uint32_t a, uint32_t& r0, uint32_t& r1,
                                      uint32_t& r2, uint32_t& r3) {
    asm volatile("ldmatrix.sync.aligned.m8n8.x4.trans.shared.b16 {%0,%1,%2,%3}, [%4];"
                 : "=r"(r0), "=r"(r1), "=r"(r2), "=r"(r3) : "r"(a));
}
// fp32-accumulator MMA (PV + ones-column row sums)
__device__ __forceinline__ void mma16816(float* c,
                                         uint32_t a0, uint32_t a1, uint32_t a2, uint32_t a3,
                                         uint32_t b0, uint32_t b1) {
    asm volatile("mma.sync.aligned.m16n8k16.row.col.f32.f16.f16.f32 "
                 "{%0,%1,%2,%3},{%4,%5,%6,%7},{%8,%9},{%0,%1,%2,%3};"
                 : "+f"(c[0]), "+f"(c[1]), "+f"(c[2]), "+f"(c[3])
                 : "r"(a0), "r"(a1), "r"(a2), "r"(a3), "r"(b0), "r"(b1));
}
// fp16-accumulator MMA (QK): D layout = {col tg2, tg2+1} half2 per lane
__device__ __forceinline__ void mma16816h(uint32_t& d0, uint32_t& d1,
                                          uint32_t a0, uint32_t a1, uint32_t a2, uint32_t a3,
                                          uint32_t b0, uint32_t b1) {
    asm volatile("mma.sync.aligned.m16n8k16.row.col.f16.f16.f16.f16 "
                 "{%0,%1},{%2,%3,%4,%5},{%6,%7},{%0,%1};"
                 : "+r"(d0), "+r"(d1)
                 : "r"(a0), "r"(a1), "r"(a2), "r"(a3), "r"(b0), "r"(b1));
}
__device__ __forceinline__ uint32_t ex2h2(uint32_t x) {
    asm("ex2.approx.f16x2 %0, %1;" : "=r"(x) : "r"(x));
    return x;
}
__device__ __forceinline__ void cpa16(uint32_t dst, const void* src) {
    asm volatile("cp.async.ca.shared.global [%0], [%1], 16;" :: "r"(dst), "l"(src));
}
__device__ __forceinline__ uint32_t ld32h(const __half* p) {
    return *reinterpret_cast<const uint32_t*>(p);
}

// ---------------------------------------------------------------------------
// Kernel 1: gather + layout transform.  grid = 8b*3p*8head*16h4 = 3072
// ---------------------------------------------------------------------------
__global__ void __launch_bounds__(256)
gather_kernel(const float* __restrict__ temp)
{
    extern __shared__ __half tileA[];  // [4 h][64 w][38 c-padded]
    const int bid = blockIdx.x, tid = threadIdx.x;
    const int h16  = bid & 15;
    const int head = (bid >> 4) & 7;
    const int bp   = bid >> 7;          // b*3 + p
    const int p    = bp % 3;
    const int b    = bp / 3;

    const size_t base = ((size_t)bp * 256 + head * 32) * 4096 + (size_t)(h16 * 4) * 64;
    // Q carries SCALE * log2(e) so QK^T lands directly in the exp2 domain
    const float scale = (p == 0) ? (0.17677669529663687f * 1.4426950408889634f) : 1.0f;

#pragma unroll
    for (int j = tid; j < 1024; j += 256) {
        const int w4 = j & 15, h = (j >> 4) & 3, c2 = j >> 6;
        const int c = c2 * 2;
        const float4 va = *reinterpret_cast<const float4*>(
            temp + base + (size_t)c * 4096 + h * 64 + w4 * 4);
        const float4 vb = *reinterpret_cast<const float4*>(
            temp + base + (size_t)(c + 1) * 4096 + h * 64 + w4 * 4);
        const int sb = (h * 64 + w4 * 4) * 38 + c;
        *reinterpret_cast<__half2*>(&tileA[sb])       = __floats2half2_rn(va.x * scale, vb.x * scale);
        *reinterpret_cast<__half2*>(&tileA[sb + 38])  = __floats2half2_rn(va.y * scale, vb.y * scale);
        *reinterpret_cast<__half2*>(&tileA[sb + 76])  = __floats2half2_rn(va.z * scale, vb.z * scale);
        *reinterpret_cast<__half2*>(&tileA[sb + 114]) = __floats2half2_rn(va.w * scale, vb.w * scale);
    }
    __syncthreads();

    // phase 2: 8 lanes per token, uint2 (8B) stores
    const int wb = (b * 8 + head) * 16;
    const int d  = (tid & 7) * 4;
#pragma unroll
    for (int pp = tid >> 3; pp < 256; pp += 32) {
        const int h = pp >> 6, w = pp & 63;
        const int win = wb + (w & 15);
        const int t   = (h16 * 4 + h) * 4 + (w >> 4);
        const int sb  = (h * 64 + w) * 38 + d;
        uint2 val;
        val.x = *reinterpret_cast<const uint32_t*>(&tileA[sb]);
        val.y = *reinterpret_cast<const uint32_t*>(&tileA[sb + 2]);
        *reinterpret_cast<uint2*>(&g_qkv[(((size_t)win * 3 + p) * 256 + t) * 32 + d]) = val;
    }
}

// ---------------------------------------------------------------------------
// Kernel 2: streaming attention + fused LePE.  grid = 1024 windows, 256 thr
//           8 warps, one strip-pair (32 query rows) per warp  [round-14]
// ---------------------------------------------------------------------------
__global__ void __launch_bounds__(256, 2)
attn_kernel(const float* __restrict__ wgt, const float* __restrict__ bias)
{
    const int win  = blockIdx.x;
    const int tid  = threadIdx.x;
    const int lane = tid & 31;
    const int wid  = tid >> 5;          // 0..7

    extern __shared__ char smem[];
    __half* sK  = reinterpret_cast<__half*>(smem);            // [256][40]
    __half* sV  = reinterpret_cast<__half*>(smem + 20480);    // [256][40]
    float2* sW2 = reinterpret_cast<float2*>(smem + 40960);    // [16 chpair][9 tap]
    float2* sB2 = reinterpret_cast<float2*>(smem + 42112);    // [16]

    const int head  = (win >> 4) & 7;
    const int cbase = head * 32;

    const uint32_t kb = (uint32_t)__cvta_generic_to_shared(sK);
    const uint32_t vb = (uint32_t)__cvta_generic_to_shared(sV);

    const __half* qkvg = g_qkv + (size_t)win * 3u * 8192u;
    const uint4* srcK = reinterpret_cast<const uint4*>(qkvg + 8192);
    const uint4* srcV = reinterpret_cast<const uint4*>(qkvg + 16384);

    // pipelined staging: 4 commit groups of 64 tokens (256 uint4), 1 iter each
#pragma unroll
    for (int gr = 0; gr < 4; ++gr) {
        const int j = gr * 256 + tid;
        const int t = j >> 2, dd = (j & 3) * 8;
        const uint32_t off = (uint32_t)(t * 40 + dd) * 2;
        cpa16(kb + off, srcK + j);
        cpa16(vb + off, srcV + j);
        asm volatile("cp.async.commit_group;");
    }

    // overlap with async window: channel-paired conv weights/bias + Q frags
    if (tid < 144) {
        const int cp = tid / 9, k = tid % 9;
        sW2[tid] = make_float2(wgt[(cbase + 2 * cp) * 9 + k],
                               wgt[(cbase + 2 * cp + 1) * 9 + k]);
    }
    if (tid < 16) sB2[tid] = make_float2(bias[cbase + 2 * tid],
                                         bias[cbase + 2 * tid + 1]);

    const int g   = lane >> 2;
    const int tg2 = (lane & 3) << 1;

    // per-warp Q fragments for its strip pair (rows wid*32 .. wid*32+31)
    uint32_t qf[2][8];
#pragma unroll
    for (int u = 0; u < 2; ++u) {
        const int r0 = (wid * 2 + u) * 16;
        const __half* q0 = qkvg + (r0 + g) * 32 + tg2;
        const __half* q1 = qkvg + (r0 + g + 8) * 32 + tg2;
        qf[u][0] = ld32h(q0);      qf[u][1] = ld32h(q1);
        qf[u][2] = ld32h(q0 + 8);  qf[u][3] = ld32h(q1 + 8);
        qf[u][4] = ld32h(q0 + 16); qf[u][5] = ld32h(q1 + 16);
        qf[u][6] = ld32h(q0 + 24); qf[u][7] = ld32h(q1 + 24);
    }

    // group 0 (tokens 0-63) ready -> start computing
    asm volatile("cp.async.wait_group 3;");
    __syncthreads();

    const int lrow = lane & 15;
    const int lcol = (lane >> 4) << 3;

    // ones-column B fragment: lanes 0-3 own n=0 column (1.0 for all k)
    const uint32_t onesB = ((lane >> 2) == 0) ? 0x3C003C00u : 0u;

    __half* og16 = g_o16 + (size_t)win * 8192;

    float o[2][4][4];
    float ol[2][4];
#pragma unroll
    for (int u = 0; u < 2; ++u) {
        ol[u][0] = 0.f; ol[u][1] = 0.f; ol[u][2] = 0.f; ol[u][3] = 0.f;
#pragma unroll
        for (int on = 0; on < 4; ++on) {
            o[u][on][0] = 0.f; o[u][on][1] = 0.f;
            o[u][on][2] = 0.f; o[u][on][3] = 0.f;
        }
    }

    uint32_t kf[2][8], vf[2][8];
    ldm4 (kb + (uint32_t)((lrow * 40 + lcol) * 2),        kf[0][0], kf[0][1], kf[0][2], kf[0][3]);
    ldm4 (kb + (uint32_t)((lrow * 40 + 16 + lcol) * 2),   kf[0][4], kf[0][5], kf[0][6], kf[0][7]);
    ldm4t(vb + (uint32_t)((lrow * 40 + lcol) * 2),        vf[0][0], vf[0][1], vf[0][2], vf[0][3]);
    ldm4t(vb + (uint32_t)((lrow * 40 + 16 + lcol) * 2),   vf[0][4], vf[0][5], vf[0][6], vf[0][7]);

#pragma unroll
    for (int kt = 0; kt < 16; ++kt) {
        // progressive staging waits; prefetch of chunk kt+1 crosses groups at 3/7/11
        if (kt == 3)  { asm volatile("cp.async.wait_group 2;"); __syncthreads(); }
        if (kt == 7)  { asm volatile("cp.async.wait_group 1;"); __syncthreads(); }
        if (kt == 11) { asm volatile("cp.async.wait_group 0;"); __syncthreads(); }

        const int cur = kt & 1;
        const int nxt = cur ^ 1;
        if (kt < 15) {
            const uint32_t rb = (uint32_t)(((kt + 1) * 16 + lrow) * 40) * 2;
            ldm4 (kb + rb + lcol * 2,        kf[nxt][0], kf[nxt][1], kf[nxt][2], kf[nxt][3]);
            ldm4 (kb + rb + (16 + lcol) * 2, kf[nxt][4], kf[nxt][5], kf[nxt][6], kf[nxt][7]);
            ldm4t(vb + rb + lcol * 2,        vf[nxt][0], vf[nxt][1], vf[nxt][2], vf[nxt][3]);
            ldm4t(vb + rb + (16 + lcol) * 2, vf[nxt][4], vf[nxt][5], vf[nxt][6], vf[nxt][7]);
        }

#pragma unroll
        for (int u = 0; u < 2; ++u) {
            uint32_t s0 = 0u, s1 = 0u, s2 = 0u, s3 = 0u;
            mma16816h(s0, s1, qf[u][0], qf[u][1], qf[u][2], qf[u][3], kf[cur][0], kf[cur][2]);
            mma16816h(s0, s1, qf[u][4], qf[u][5], qf[u][6], qf[u][7], kf[cur][4], kf[cur][6]);
            mma16816h(s2, s3, qf[u][0], qf[u][1], qf[u][2], qf[u][3], kf[cur][1], kf[cur][3]);
            mma16816h(s2, s3, qf[u][4], qf[u][5], qf[u][6], qf[u][7], kf[cur][5], kf[cur][7]);

            // exp2 directly on the f16 MMA output (log2 domain; no max)
            const uint32_t p0 = ex2h2(s0);
            const uint32_t p1 = ex2h2(s1);
            const uint32_t p2 = ex2h2(s2);
            const uint32_t p3 = ex2h2(s3);

            mma16816(o[u][0], p0, p1, p2, p3, vf[cur][0], vf[cur][1]);
            mma16816(o[u][1], p0, p1, p2, p3, vf[cur][2], vf[cur][3]);
            mma16816(o[u][2], p0, p1, p2, p3, vf[cur][4], vf[cur][5]);
            mma16816(o[u][3], p0, p1, p2, p3, vf[cur][6], vf[cur][7]);
            mma16816(ol[u], p0, p1, p2, p3, onesB, onesB);
        }
    }

#pragma unroll
    for (int u = 0; u < 2; ++u) {
        const int r0 = (wid * 2 + u) * 16;
        const float l0 = __shfl_sync(0xffffffffu, ol[u][0], lane & 28);
        const float l1 = __shfl_sync(0xffffffffu, ol[u][2], lane & 28);
        const float inv0 = 1.f / l0;
        const float inv1 = 1.f / l1;

        // epilogue: normalize + LePE conv (float2 weights) + half2 store
#pragma unroll
        for (int on = 0; on < 4; ++on) {
            const int d0 = on * 8 + tg2;
            const float2* wrow = &sW2[(d0 >> 1) * 9];
            const float2  b2   = sB2[d0 >> 1];
#pragma unroll
            for (int ocp = 0; ocp < 4; ocp += 2) {
                const int t  = r0 + g + ((ocp & 2) ? 8 : 0);
                const int ih = t >> 2;
                const int jw = t & 3;
                float a0 = b2.x, a1 = b2.y;
                const int ki0 = (ih == 0) ? 1 : 0;
                const int ki1 = (ih == 63) ? 2 : 3;
#pragma unroll
                for (int ki = 0; ki < 3; ++ki) {
                    if (ki < ki0 || ki >= ki1) continue;
                    const int ii = ih + ki - 1;
#pragma unroll
                    for (int kj = 0; kj < 3; ++kj) {
                        const int jj = jw + kj - 1;
                        if (jj < 0 || jj > 3) continue;
                        const __half2 vv = *reinterpret_cast<const __half2*>(
                            &sV[(ii * 4 + jj) * 40 + d0]);
                        const float2 vf2 = __half22float2(vv);
                        const float2 wv  = wrow[ki * 3 + kj];
                        a0 = fmaf(wv.x, vf2.x, a0);
                        a1 = fmaf(wv.y, vf2.y, a1);
                    }
                }
                const float inv = (ocp & 2) ? inv1 : inv0;
                const __half2 r = __floats2half2_rn(o[u][on][ocp] * inv + a0,
                                                    o[u][on][ocp + 1] * inv + a1);
                *reinterpret_cast<__half2*>(&og16[t * 32 + d0]) = r;
            }
        }
    }
}

// ---------------------------------------------------------------------------
// Kernel 3: scatter to (B,C,H,W).  grid = 8(b)*8(head)*16(h4) = 1024
//           4-h-row tiles, smem 17 KB -> high CTA residency
// ---------------------------------------------------------------------------
__global__ void __launch_bounds__(256)
scatter_kernel(float* __restrict__ out)
{
    extern __shared__ __half tileC[];  // [32 c][4 h][64 w]: c-stride 266, h-stride 66
    const int bid = blockIdx.x, tid = threadIdx.x;
    const int h4   = bid & 15;
    const int head = (bid >> 4) & 7;
    const int b    = bid >> 7;
    const int h0   = h4 * 4;
    const int lane = tid & 31, wid = tid >> 5;
    const int wb   = (b * 8 + head) * 16;
    const int d0   = (lane & 15) * 2;
    const int hiL  = lane >> 4;

    // phase 1: coalesced reads; shuffle-pair to build w-adjacent half2 of one
    // channel per lane, single STS.32 (word-stride 133 per c: conflict-free)
#pragma unroll
    for (int pp = wid; pp < 128; pp += 8) {
        const int p2 = pp * 2 + hiL;
        const int h = p2 >> 6, w = p2 & 63;
        const int win = wb + (w & 15);
        const int t   = (h0 + h) * 4 + (w >> 4);
        const uint32_t mine = *reinterpret_cast<const uint32_t*>(
            &g_o16[((size_t)win * 256 + t) * 32 + d0]);
        const uint32_t other = __shfl_xor_sync(0xffffffffu, mine, 16);
        uint32_t pairv;
        if (hiL == 0) {
            pairv = (mine & 0xFFFFu) | (other << 16);
        } else {
            pairv = (other >> 16) | (mine & 0xFFFF0000u);
        }
        const int c = d0 + hiL;
        const int weven = w & ~1;
        *reinterpret_cast<uint32_t*>(&tileC[c * 266 + h * 66 + weven]) = pairv;
    }
    __syncthreads();

    // phase 2: vectorized write, STG.128, 512B contiguous per warp
    const size_t ob = ((size_t)b * 256 + head * 32) * 4096 + (size_t)h0 * 64;
#pragma unroll
    for (int j = tid; j < 2048; j += 256) {
        const int w4 = j & 15, h = (j >> 4) & 3, c = j >> 6;
        const int sbase = c * 266 + h * 66 + w4 * 4;
        const float2 fa = __half22float2(*reinterpret_cast<const __half2*>(&tileC[sbase]));
        const float2 fb = __half22float2(*reinterpret_cast<const __half2*>(&tileC[sbase + 2]));
        float4 r;
        r.x = fa.x; r.y = fa.y; r.z = fb.x; r.w = fb.y;
        *reinterpret_cast<float4*>(&out[ob + (size_t)c * 4096 + h * 64 + w4 * 4]) = r;
    }
}

// ---------------------------------------------------------------------------
extern "C" void kernel_launch(void* const* d_in, const int* in_sizes, int n_in,
                              void* d_out, int out_size)
{
    (void)in_sizes; (void)n_in; (void)out_size;
    const float* temp = (const float*)d_in[0];
    const float* wgt  = (const float*)d_in[1];
    const float* bias = (const float*)d_in[2];
    float* out = (float*)d_out;

    cudaFuncSetAttribute(gather_kernel,  cudaFuncAttributeMaxDynamicSharedMemorySize, SMEM_A);
    cudaFuncSetAttribute(attn_kernel,    cudaFuncAttributeMaxDynamicSharedMemorySize, SMEM_B);
    cudaFuncSetAttribute(scatter_kernel, cudaFuncAttributeMaxDynamicSharedMemorySize, SMEM_C);

    gather_kernel<<<3072, 256, SMEM_A>>>(temp);
    attn_kernel<<<1024, 256, SMEM_B>>>(wgt, bias);
    scatter_kernel<<<1024, 256, SMEM_C>>>(out);
}

// round 17
// speedup vs baseline: 1.1497x; 1.0005x over previous
#include <cuda_runtime.h>
#include <cuda_fp16.h>
#include <stdint.h>

// 3-kernel pipeline (single stream):
//  1) gather_kernel : temp fp32 -> g_qkv[win][qkv][t][d] fp16; Q pre-scaled by SCALE*log2e
//                     NOW 128-thread CTAs, 2-h-row tiles (grid 6144) for latency hiding
//  2) attn_kernel   : streaming no-max softmax attention + fused LePE -> g_o16 fp16
//                     f16-acc QK MMA; ones-column MMA row-sums; pipelined cg staging;
//                     8 warps/CTA, one strip-pair per warp  [round-14 core]
//  3) scatter_kernel: g_o16 -> out (B,C,H,W); 4-h-row tiles, shuffle-paired STS.32,
//                     STG.128  [round-16]

#define SMEM_A 9728    // half[2][64][38]
#define SMEM_B 42240   // sK/sV half[256][40] + sW2 float2[16][9] + sB2 float2[16]
#define SMEM_C 17152   // half[32][266]  (c-stride 266, h-stride 66)

__device__ __half g_qkv[1024u * 3u * 256u * 32u];  // 48 MB
__device__ __half g_o16[1024u * 256u * 32u];       // 16 MB

__device__ __forceinline__ void ldm4(uint32_t a, uint32_t& r0, uint32_t& r1,
                                     uint32_t& r2, uint32_t& r3) {
    asm volatile("ldmatrix.sync.aligned.m8n8.x4.shared.b16 {%0,%1,%2,%3}, [%4];"
                 : "=r"(r0), "=r"(r1), "=r"(r2), "=r"(r3) : "r"(a));
}
__device__ __forceinline__ void ldm4t(uint32_t a, uint32_t& r0, uint32_t& r1,
                                      uint32_t& r2, uint32_t& r3) {
    asm volatile("ldmatrix.sync.aligned.m8n8.x4.trans.shared.b16 {%0,%1,%2,%3}, [%4];"
                 : "=r"(r0), "=r"(r1), "=r"(r2), "=r"(r3) : "r"(a));
}
// fp32-accumulator MMA (PV + ones-column row sums)
__device__ __forceinline__ void mma16816(float* c,
                                         uint32_t a0, uint32_t a1, uint32_t a2, uint32_t a3,
                                         uint32_t b0, uint32_t b1) {
    asm volatile("mma.sync.aligned.m16n8k16.row.col.f32.f16.f16.f32 "
                 "{%0,%1,%2,%3},{%4,%5,%6,%7},{%8,%9},{%0,%1,%2,%3};"
                 : "+f"(c[0]), "+f"(c[1]), "+f"(c[2]), "+f"(c[3])
                 : "r"(a0), "r"(a1), "r"(a2), "r"(a3), "r"(b0), "r"(b1));
}
// fp16-accumulator MMA (QK): D layout = {col tg2, tg2+1} half2 per lane
__device__ __forceinline__ void mma16816h(uint32_t& d0, uint32_t& d1,
                                          uint32_t a0, uint32_t a1, uint32_t a2, uint32_t a3,
                                          uint32_t b0, uint32_t b1) {
    asm volatile("mma.sync.aligned.m16n8k16.row.col.f16.f16.f16.f16 "
                 "{%0,%1},{%2,%3,%4,%5},{%6,%7},{%0,%1};"
                 : "+r"(d0), "+r"(d1)
                 : "r"(a0), "r"(a1), "r"(a2), "r"(a3), "r"(b0), "r"(b1));
}
__device__ __forceinline__ uint32_t ex2h2(uint32_t x) {
    asm("ex2.approx.f16x2 %0, %1;" : "=r"(x) : "r"(x));
    return x;
}
__device__ __forceinline__ void cpa16cg(uint32_t dst, const void* src) {
    asm volatile("cp.async.cg.shared.global [%0], [%1], 16;" :: "r"(dst), "l"(src));
}
__device__ __forceinline__ uint32_t ld32h(const __half* p) {
    return *reinterpret_cast<const uint32_t*>(p);
}

// ---------------------------------------------------------------------------
// Kernel 1: gather + layout transform.  grid = 8b*3p*8head*32h2 = 6144,
//           128 threads, 2-h-row tiles
// ---------------------------------------------------------------------------
__global__ void __launch_bounds__(128)
gather_kernel(const float* __restrict__ temp)
{
    extern __shared__ __half tileA[];  // [2 h][64 w][38 c-padded]
    const int bid = blockIdx.x, tid = threadIdx.x;
    const int h32  = bid & 31;
    const int head = (bid >> 5) & 7;
    const int bp   = bid >> 8;          // b*3 + p
    const int p    = bp % 3;
    const int b    = bp / 3;

    const size_t base = ((size_t)bp * 256 + head * 32) * 4096 + (size_t)(h32 * 2) * 64;
    // Q carries SCALE * log2(e) so QK^T lands directly in the exp2 domain
    const float scale = (p == 0) ? (0.17677669529663687f * 1.4426950408889634f) : 1.0f;

#pragma unroll
    for (int j = tid; j < 512; j += 128) {
        const int w4 = j & 15, h = (j >> 4) & 1, c2 = j >> 5;
        const int c = c2 * 2;
        const float4 va = *reinterpret_cast<const float4*>(
            temp + base + (size_t)c * 4096 + h * 64 + w4 * 4);
        const float4 vb = *reinterpret_cast<const float4*>(
            temp + base + (size_t)(c + 1) * 4096 + h * 64 + w4 * 4);
        const int sb = (h * 64 + w4 * 4) * 38 + c;
        *reinterpret_cast<__half2*>(&tileA[sb])       = __floats2half2_rn(va.x * scale, vb.x * scale);
        *reinterpret_cast<__half2*>(&tileA[sb + 38])  = __floats2half2_rn(va.y * scale, vb.y * scale);
        *reinterpret_cast<__half2*>(&tileA[sb + 76])  = __floats2half2_rn(va.z * scale, vb.z * scale);
        *reinterpret_cast<__half2*>(&tileA[sb + 114]) = __floats2half2_rn(va.w * scale, vb.w * scale);
    }
    __syncthreads();

    // phase 2: 8 lanes per token, uint2 (8B) stores
    const int wb = (b * 8 + head) * 16;
    const int d  = (tid & 7) * 4;
#pragma unroll
    for (int pp = tid >> 3; pp < 128; pp += 16) {
        const int h = pp >> 6, w = pp & 63;
        const int win = wb + (w & 15);
        const int t   = (h32 * 2 + h) * 4 + (w >> 4);
        const int sb  = (h * 64 + w) * 38 + d;
        uint2 val;
        val.x = *reinterpret_cast<const uint32_t*>(&tileA[sb]);
        val.y = *reinterpret_cast<const uint32_t*>(&tileA[sb + 2]);
        *reinterpret_cast<uint2*>(&g_qkv[(((size_t)win * 3 + p) * 256 + t) * 32 + d]) = val;
    }
}

// ---------------------------------------------------------------------------
// Kernel 2: streaming attention + fused LePE.  grid = 1024 windows, 256 thr
//           8 warps, one strip-pair (32 query rows) per warp
// ---------------------------------------------------------------------------
__global__ void __launch_bounds__(256, 2)
attn_kernel(const float* __restrict__ wgt, const float* __restrict__ bias)
{
    const int win  = blockIdx.x;
    const int tid  = threadIdx.x;
    const int lane = tid & 31;
    const int wid  = tid >> 5;          // 0..7

    extern __shared__ char smem[];
    __half* sK  = reinterpret_cast<__half*>(smem);            // [256][40]
    __half* sV  = reinterpret_cast<__half*>(smem + 20480);    // [256][40]
    float2* sW2 = reinterpret_cast<float2*>(smem + 40960);    // [16 chpair][9 tap]
    float2* sB2 = reinterpret_cast<float2*>(smem + 42112);    // [16]

    const int head  = (win >> 4) & 7;
    const int cbase = head * 32;

    const uint32_t kb = (uint32_t)__cvta_generic_to_shared(sK);
    const uint32_t vb = (uint32_t)__cvta_generic_to_shared(sV);

    const __half* qkvg = g_qkv + (size_t)win * 3u * 8192u;
    const uint4* srcK = reinterpret_cast<const uint4*>(qkvg + 8192);
    const uint4* srcV = reinterpret_cast<const uint4*>(qkvg + 16384);

    // pipelined staging: 4 commit groups of 64 tokens (256 uint4), 1 iter each
#pragma unroll
    for (int gr = 0; gr < 4; ++gr) {
        const int j = gr * 256 + tid;
        const int t = j >> 2, dd = (j & 3) * 8;
        const uint32_t off = (uint32_t)(t * 40 + dd) * 2;
        cpa16cg(kb + off, srcK + j);
        cpa16cg(vb + off, srcV + j);
        asm volatile("cp.async.commit_group;");
    }

    // overlap with async window: channel-paired conv weights/bias + Q frags
    if (tid < 144) {
        const int cp = tid / 9, k = tid % 9;
        sW2[tid] = make_float2(wgt[(cbase + 2 * cp) * 9 + k],
                               wgt[(cbase + 2 * cp + 1) * 9 + k]);
    }
    if (tid < 16) sB2[tid] = make_float2(bias[cbase + 2 * tid],
                                         bias[cbase + 2 * tid + 1]);

    const int g   = lane >> 2;
    const int tg2 = (lane & 3) << 1;

    // per-warp Q fragments for its strip pair (rows wid*32 .. wid*32+31)
    uint32_t qf[2][8];
#pragma unroll
    for (int u = 0; u < 2; ++u) {
        const int r0 = (wid * 2 + u) * 16;
        const __half* q0 = qkvg + (r0 + g) * 32 + tg2;
        const __half* q1 = qkvg + (r0 + g + 8) * 32 + tg2;
        qf[u][0] = ld32h(q0);      qf[u][1] = ld32h(q1);
        qf[u][2] = ld32h(q0 + 8);  qf[u][3] = ld32h(q1 + 8);
        qf[u][4] = ld32h(q0 + 16); qf[u][5] = ld32h(q1 + 16);
        qf[u][6] = ld32h(q0 + 24); qf[u][7] = ld32h(q1 + 24);
    }

    // group 0 (tokens 0-63) ready -> start computing
    asm volatile("cp.async.wait_group 3;");
    __syncthreads();

    const int lrow = lane & 15;
    const int lcol = (lane >> 4) << 3;

    // ones-column B fragment: lanes 0-3 own n=0 column (1.0 for all k)
    const uint32_t onesB = ((lane >> 2) == 0) ? 0x3C003C00u : 0u;

    __half* og16 = g_o16 + (size_t)win * 8192;

    float o[2][4][4];
    float ol[2][4];
#pragma unroll
    for (int u = 0; u < 2; ++u) {
        ol[u][0] = 0.f; ol[u][1] = 0.f; ol[u][2] = 0.f; ol[u][3] = 0.f;
#pragma unroll
        for (int on = 0; on < 4; ++on) {
            o[u][on][0] = 0.f; o[u][on][1] = 0.f;
            o[u][on][2] = 0.f; o[u][on][3] = 0.f;
        }
    }

    uint32_t kf[2][8], vf[2][8];
    ldm4 (kb + (uint32_t)((lrow * 40 + lcol) * 2),        kf[0][0], kf[0][1], kf[0][2], kf[0][3]);
    ldm4 (kb + (uint32_t)((lrow * 40 + 16 + lcol) * 2),   kf[0][4], kf[0][5], kf[0][6], kf[0][7]);
    ldm4t(vb + (uint32_t)((lrow * 40 + lcol) * 2),        vf[0][0], vf[0][1], vf[0][2], vf[0][3]);
    ldm4t(vb + (uint32_t)((lrow * 40 + 16 + lcol) * 2),   vf[0][4], vf[0][5], vf[0][6], vf[0][7]);

#pragma unroll
    for (int kt = 0; kt < 16; ++kt) {
        // progressive staging waits; prefetch of chunk kt+1 crosses groups at 3/7/11
        if (kt == 3)  { asm volatile("cp.async.wait_group 2;"); __syncthreads(); }
        if (kt == 7)  { asm volatile("cp.async.wait_group 1;"); __syncthreads(); }
        if (kt == 11) { asm volatile("cp.async.wait_group 0;"); __syncthreads(); }

        const int cur = kt & 1;
        const int nxt = cur ^ 1;
        if (kt < 15) {
            const uint32_t rb = (uint32_t)(((kt + 1) * 16 + lrow) * 40) * 2;
            ldm4 (kb + rb + lcol * 2,        kf[nxt][0], kf[nxt][1], kf[nxt][2], kf[nxt][3]);
            ldm4 (kb + rb + (16 + lcol) * 2, kf[nxt][4], kf[nxt][5], kf[nxt][6], kf[nxt][7]);
            ldm4t(vb + rb + lcol * 2,        vf[nxt][0], vf[nxt][1], vf[nxt][2], vf[nxt][3]);
            ldm4t(vb + rb + (16 + lcol) * 2, vf[nxt][4], vf[nxt][5], vf[nxt][6], vf[nxt][7]);
        }

#pragma unroll
        for (int u = 0; u < 2; ++u) {
            uint32_t s0 = 0u, s1 = 0u, s2 = 0u, s3 = 0u;
            mma16816h(s0, s1, qf[u][0], qf[u][1], qf[u][2], qf[u][3], kf[cur][0], kf[cur][2]);
            mma16816h(s0, s1, qf[u][4], qf[u][5], qf[u][6], qf[u][7], kf[cur][4], kf[cur][6]);
            mma16816h(s2, s3, qf[u][0], qf[u][1], qf[u][2], qf[u][3], kf[cur][1], kf[cur][3]);
            mma16816h(s2, s3, qf[u][4], qf[u][5], qf[u][6], qf[u][7], kf[cur][5], kf[cur][7]);

            // exp2 directly on the f16 MMA output (log2 domain; no max)
            const uint32_t p0 = ex2h2(s0);
            const uint32_t p1 = ex2h2(s1);
            const uint32_t p2 = ex2h2(s2);
            const uint32_t p3 = ex2h2(s3);

            mma16816(o[u][0], p0, p1, p2, p3, vf[cur][0], vf[cur][1]);
            mma16816(o[u][1], p0, p1, p2, p3, vf[cur][2], vf[cur][3]);
            mma16816(o[u][2], p0, p1, p2, p3, vf[cur][4], vf[cur][5]);
            mma16816(o[u][3], p0, p1, p2, p3, vf[cur][6], vf[cur][7]);
            mma16816(ol[u], p0, p1, p2, p3, onesB, onesB);
        }
    }

#pragma unroll
    for (int u = 0; u < 2; ++u) {
        const int r0 = (wid * 2 + u) * 16;
        const float l0 = __shfl_sync(0xffffffffu, ol[u][0], lane & 28);
        const float l1 = __shfl_sync(0xffffffffu, ol[u][2], lane & 28);
        const float inv0 = 1.f / l0;
        const float inv1 = 1.f / l1;

        // epilogue: normalize + LePE conv (float2 weights) + half2 store
#pragma unroll
        for (int on = 0; on < 4; ++on) {
            const int d0 = on * 8 + tg2;
            const float2* wrow = &sW2[(d0 >> 1) * 9];
            const float2  b2   = sB2[d0 >> 1];
#pragma unroll
            for (int ocp = 0; ocp < 4; ocp += 2) {
                const int t  = r0 + g + ((ocp & 2) ? 8 : 0);
                const int ih = t >> 2;
                const int jw = t & 3;
                float a0 = b2.x, a1 = b2.y;
                const int ki0 = (ih == 0) ? 1 : 0;
                const int ki1 = (ih == 63) ? 2 : 3;
#pragma unroll
                for (int ki = 0; ki < 3; ++ki) {
                    if (ki < ki0 || ki >= ki1) continue;
                    const int ii = ih + ki - 1;
#pragma unroll
                    for (int kj = 0; kj < 3; ++kj) {
                        const int jj = jw + kj - 1;
                        if (jj < 0 || jj > 3) continue;
                        const __half2 vv = *reinterpret_cast<const __half2*>(
                            &sV[(ii * 4 + jj) * 40 + d0]);
                        const float2 vf2 = __half22float2(vv);
                        const float2 wv  = wrow[ki * 3 + kj];
                        a0 = fmaf(wv.x, vf2.x, a0);
                        a1 = fmaf(wv.y, vf2.y, a1);
                    }
                }
                const float inv = (ocp & 2) ? inv1 : inv0;
                const __half2 r = __floats2half2_rn(o[u][on][ocp] * inv + a0,
                                                    o[u][on][ocp + 1] * inv + a1);
                *reinterpret_cast<__half2*>(&og16[t * 32 + d0]) = r;
            }
        }
    }
}

// ---------------------------------------------------------------------------
// Kernel 3: scatter to (B,C,H,W).  grid = 8(b)*8(head)*16(h4) = 1024
//           4-h-row tiles, smem 17 KB -> high CTA residency
// ---------------------------------------------------------------------------
__global__ void __launch_bounds__(256)
scatter_kernel(float* __restrict__ out)
{
    extern __shared__ __half tileC[];  // [32 c][4 h][64 w]: c-stride 266, h-stride 66
    const int bid = blockIdx.x, tid = threadIdx.x;
    const int h4   = bid & 15;
    const int head = (bid >> 4) & 7;
    const int b    = bid >> 7;
    const int h0   = h4 * 4;
    const int lane = tid & 31, wid = tid >> 5;
    const int wb   = (b * 8 + head) * 16;
    const int d0   = (lane & 15) * 2;
    const int hiL  = lane >> 4;

    // phase 1: coalesced reads; shuffle-pair to build w-adjacent half2 of one
    // channel per lane, single STS.32 (word-stride 133 per c: conflict-free)
#pragma unroll
    for (int pp = wid; pp < 128; pp += 8) {
        const int p2 = pp * 2 + hiL;
        const int h = p2 >> 6, w = p2 & 63;
        const int win = wb + (w & 15);
        const int t   = (h0 + h) * 4 + (w >> 4);
        const uint32_t mine = *reinterpret_cast<const uint32_t*>(
            &g_o16[((size_t)win * 256 + t) * 32 + d0]);
        const uint32_t other = __shfl_xor_sync(0xffffffffu, mine, 16);
        uint32_t pairv;
        if (hiL == 0) {
            pairv = (mine & 0xFFFFu) | (other << 16);
        } else {
            pairv = (other >> 16) | (mine & 0xFFFF0000u);
        }
        const int c = d0 + hiL;
        const int weven = w & ~1;
        *reinterpret_cast<uint32_t*>(&tileC[c * 266 + h * 66 + weven]) = pairv;
    }
    __syncthreads();

    // phase 2: vectorized write, STG.128, 512B contiguous per warp
    const size_t ob = ((size_t)b * 256 + head * 32) * 4096 + (size_t)h0 * 64;
#pragma unroll
    for (int j = tid; j < 2048; j += 256) {
        const int w4 = j & 15, h = (j >> 4) & 3, c = j >> 6;
        const int sbase = c * 266 + h * 66 + w4 * 4;
        const float2 fa = __half22float2(*reinterpret_cast<const __half2*>(&tileC[sbase]));
        const float2 fb = __half22float2(*reinterpret_cast<const __half2*>(&tileC[sbase + 2]));
        float4 r;
        r.x = fa.x; r.y = fa.y; r.z = fb.x; r.w = fb.y;
        *reinterpret_cast<float4*>(&out[ob + (size_t)c * 4096 + h * 64 + w4 * 4]) = r;
    }
}

// ---------------------------------------------------------------------------
extern "C" void kernel_launch(void* const* d_in, const int* in_sizes, int n_in,
                              void* d_out, int out_size)
{
    (void)in_sizes; (void)n_in; (void)out_size;
    const float* temp = (const float*)d_in[0];
    const float* wgt  = (const float*)d_in[1];
    const float* bias = (const float*)d_in[2];
    float* out = (float*)d_out;

    cudaFuncSetAttribute(gather_kernel,  cudaFuncAttributeMaxDynamicSharedMemorySize, SMEM_A);
    cudaFuncSetAttribute(attn_kernel,    cudaFuncAttributeMaxDynamicSharedMemorySize, SMEM_B);
    cudaFuncSetAttribute(scatter_kernel, cudaFuncAttributeMaxDynamicSharedMemorySize, SMEM_C);

    gather_kernel<<<6144, 128, SMEM_A>>>(temp);
    attn_kernel<<<1024, 256, SMEM_B>>>(wgt, bias);
    scatter_kernel<<<1024, 256, SMEM_C>>>(out);
}